// round 14
// baseline (speedup 1.0000x reference)
#include <cuda_runtime.h>
#include <cuda_bf16.h>
#include <cuda_fp16.h>
#include <math.h>

// Problem constants (shapes are fixed for this problem instance)
#define NN      100000
#define NE      3200000
#define FIN     512
#define HID     64
#define NCLS    47
#define KHOPS   10
#define ALPHA   0.1f

// -------- device scratch (no allocations allowed) --------
__device__ int   g_count[NN];        // in-degree counts (real edges only)
__device__ int   g_colptr[NN + 1];   // CSR row pointers (by destination)
__device__ int   g_cursor[NN];       // scatter cursors
__device__ float g_dis[NN];          // D^-1/2 (deg incl. self loop)
__device__ int   g_incl[NN];         // inclusive per-block scan temp
__device__ int   g_blksum[256];      // block sums for scan
__device__ __align__(16) int g_edge[NE + 8];  // src index, sorted by dst (+pad)
__device__ __align__(16) __half g_Wt[(size_t)HID * FIN];  // W^T fp16 [64][512]
__device__ __align__(256) __half2 g_h0h[(size_t)NN * 32]; // fp16 anchor (unscaled h0)
__device__ __align__(256) float g_hF[(size_t)NN * HID];   // final fp32 h
__device__ __align__(256) __half2 g_hsA[(size_t)NN * 32]; // scaled fp16 state
__device__ __align__(256) __half2 g_hsB[(size_t)NN * 32];

// ---------------- CSR build ----------------
__global__ void k_hist(const int* __restrict__ col, int e) {
    int i4 = (blockIdx.x * blockDim.x + threadIdx.x) * 4;
    if (i4 + 4 <= e) {
        int4 c = *(const int4*)(col + i4);
        atomicAdd(&g_count[c.x], 1);
        atomicAdd(&g_count[c.y], 1);
        atomicAdd(&g_count[c.z], 1);
        atomicAdd(&g_count[c.w], 1);
    } else {
        for (int i = i4; i < e; i++) atomicAdd(&g_count[col[i]], 1);
    }
}

// Hillis-Steele block scan (1024/block); also computes g_dis
__global__ void k_scan_block(int n) {
    __shared__ int s[1024];
    int i = blockIdx.x * 1024 + threadIdx.x;
    int v = (i < n) ? g_count[i] : 0;
    if (i < n) g_dis[i] = rsqrtf((float)(v + 1));  // +1 self loop
    s[threadIdx.x] = v;
    __syncthreads();
    #pragma unroll
    for (int off = 1; off < 1024; off <<= 1) {
        int t = (threadIdx.x >= off) ? s[threadIdx.x - off] : 0;
        __syncthreads();
        s[threadIdx.x] += t;
        __syncthreads();
    }
    if (i < n) g_incl[i] = s[threadIdx.x];
    if (threadIdx.x == 1023) g_blksum[blockIdx.x] = s[1023];
}

// warp-parallel exclusive scan of block sums (shfl scan, chunks of 32)
__global__ void k_scan_sums(int nb) {
    int lane = threadIdx.x & 31;
    int carry = 0;
    for (int base = 0; base < nb; base += 32) {
        int i = base + lane;
        int orig = (i < nb) ? g_blksum[i] : 0;
        int v = orig;
        #pragma unroll
        for (int off = 1; off < 32; off <<= 1) {
            int t = __shfl_up_sync(0xffffffffu, v, off);
            if (lane >= off) v += t;
        }
        if (i < nb) g_blksum[i] = (v - orig) + carry;   // exclusive + carry
        carry += __shfl_sync(0xffffffffu, v, 31);       // chunk total
    }
}

__global__ void k_finalize(int n) {
    int i = blockIdx.x * blockDim.x + threadIdx.x;
    if (i == 0) g_colptr[0] = 0;
    if (i < n) {
        int e = g_incl[i] + g_blksum[i >> 10];
        g_colptr[i + 1] = e;
        g_cursor[i] = e - g_count[i];
    }
}

__global__ void k_scatter_edges(const int* __restrict__ row, const int* __restrict__ col, int e) {
    int i = blockIdx.x * blockDim.x + threadIdx.x;
    if (i >= e) return;
    int c = col[i];
    int pos = atomicAdd(&g_cursor[c], 1);
    g_edge[pos] = row[i];
}

// ---------------- W preconvert: g_Wt[n][k] = (half)W[k][n] ----------------
__global__ void k_wconv(const float* __restrict__ W) {
    int i = blockIdx.x * blockDim.x + threadIdx.x;
    if (i < FIN * HID) {
        int k = i >> 6, nn = i & 63;
        g_Wt[(size_t)nn * FIN + k] = __float2half(W[(size_t)k * HID + nn]);
    }
}

// ---------------- Embed GEMM: W-in-smem (2 phases), X fragments from global ------
// H0 = relu(X @ W + b). Only W staged in shared; each thread LDG.64s exactly its
// mma A-pair from X and converts in registers (identical rn rounding). No X smem,
// no per-chunk barriers. Warp tile = 16 rows x 64 cols, acc layout unchanged.
#define KPH  256            // K per phase
#define PSTR 264            // padded W smem row stride in halves (bank-conflict-free)
__global__ __launch_bounds__(256, 2) void k_embed_mma(const float* __restrict__ X,
                                                      const float* __restrict__ b, int n) {
    __shared__ __align__(16) __half Ws[64][PSTR];   // 33.8 KB
    __shared__ float bs[HID];
    int tid = threadIdx.x;
    int wid = tid >> 5, lane = tid & 31;
    int g  = lane >> 2;          // 0..7
    int cq = (lane & 3) * 2;     // 0,2,4,6
    int rowBase = blockIdx.x * 128;
    if (tid < HID) bs[tid] = b[tid];

    int r0 = rowBase + wid * 16 + g;
    int r1 = r0 + 8;
    int r0c = (r0 < n) ? r0 : (n - 1);
    int r1c = (r1 < n) ? r1 : (n - 1);
    const float* x0 = X + (size_t)r0c * FIN;
    const float* x1 = X + (size_t)r1c * FIN;

    float acc[8][4];
    #pragma unroll
    for (int i = 0; i < 8; i++)
        #pragma unroll
        for (int j = 0; j < 4; j++) acc[i][j] = 0.f;

    // W load assignment: 4 threads/row, 64 halves (8 uint4) each
    int wr = tid >> 2;
    int wq = (tid & 3) * 64;

    float2 pa0, pa1, pa2, pa3;

    #pragma unroll
    for (int p = 0; p < 2; p++) {
        int kbase = p * KPH;
        if (p) __syncthreads();          // drain reads of previous phase
        {
            const uint4* src = (const uint4*)(g_Wt + (size_t)wr * FIN + kbase + wq);
            uint4* dst = (uint4*)&Ws[wr][wq];
            #pragma unroll
            for (int t = 0; t < 8; t++) dst[t] = src[t];
        }
        __syncthreads();

        // prefetch first A pairs of this phase
        pa0 = *(const float2*)(x0 + kbase + cq);
        pa1 = *(const float2*)(x1 + kbase + cq);
        pa2 = *(const float2*)(x0 + kbase + cq + 8);
        pa3 = *(const float2*)(x1 + kbase + cq + 8);

        #pragma unroll
        for (int kk = 0; kk < KPH; kk += 16) {
            __half2 h0 = __floats2half2_rn(pa0.x, pa0.y);
            __half2 h1 = __floats2half2_rn(pa1.x, pa1.y);
            __half2 h2 = __floats2half2_rn(pa2.x, pa2.y);
            __half2 h3 = __floats2half2_rn(pa3.x, pa3.y);
            unsigned a0 = *(unsigned*)&h0;
            unsigned a1 = *(unsigned*)&h1;
            unsigned a2 = *(unsigned*)&h2;
            unsigned a3 = *(unsigned*)&h3;
            // prefetch next kk (crosses into next phase's K range at phase end)
            if (kk + 16 < KPH || p == 0) {
                int nx = (kk + 16 < KPH) ? (kbase + kk + 16) : KPH;
                pa0 = *(const float2*)(x0 + nx + cq);
                pa1 = *(const float2*)(x1 + nx + cq);
                pa2 = *(const float2*)(x0 + nx + cq + 8);
                pa3 = *(const float2*)(x1 + nx + cq + 8);
            }
            #pragma unroll
            for (int cb = 0; cb < 8; cb++) {
                unsigned b0 = *(const unsigned*)&Ws[cb * 8 + g][kk + cq];
                unsigned b1 = *(const unsigned*)&Ws[cb * 8 + g][kk + cq + 8];
                asm volatile(
                    "mma.sync.aligned.m16n8k16.row.col.f32.f16.f16.f32 "
                    "{%0,%1,%2,%3}, {%4,%5,%6,%7}, {%8,%9}, {%0,%1,%2,%3};"
                    : "+f"(acc[cb][0]), "+f"(acc[cb][1]),
                      "+f"(acc[cb][2]), "+f"(acc[cb][3])
                    : "r"(a0), "r"(a1), "r"(a2), "r"(a3), "r"(b0), "r"(b1));
            }
        }
    }

    // epilogue: bias + relu -> fp16 anchor g_h0h only (no dis dependency)
    #pragma unroll
    for (int cb = 0; cb < 8; cb++) {
        int c = cb * 8 + cq;
        float bx = bs[c], by = bs[c + 1];
        if (r0 < n) {
            float v0 = fmaxf(acc[cb][0] + bx, 0.f);
            float v1 = fmaxf(acc[cb][1] + by, 0.f);
            g_h0h[(size_t)r0 * 32 + (c >> 1)] = __floats2half2_rn(v0, v1);
        }
        if (r1 < n) {
            float v0 = fmaxf(acc[cb][2] + bx, 0.f);
            float v1 = fmaxf(acc[cb][3] + by, 0.f);
            g_h0h[(size_t)r1 * 32 + (c >> 1)] = __floats2half2_rn(v0, v1);
        }
    }
}

// ---------------- hsA = dis (.) h0h  (initial scaled state) ----------------
__global__ __launch_bounds__(256) void k_scale(int n) {
    int idx = blockIdx.x * blockDim.x + threadIdx.x;
    int total = n * 8;
    if (idx >= total) return;
    int v = idx >> 3;
    float d = g_dis[v];
    uint4 hv = ((const uint4*)g_h0h)[idx];
    float2 f0 = __half22float2(*(__half2*)&hv.x);
    float2 f1 = __half22float2(*(__half2*)&hv.y);
    float2 f2 = __half22float2(*(__half2*)&hv.z);
    float2 f3 = __half22float2(*(__half2*)&hv.w);
    __half2 p0 = __floats2half2_rn(d * f0.x, d * f0.y);
    __half2 p1 = __floats2half2_rn(d * f1.x, d * f1.y);
    __half2 p2 = __floats2half2_rn(d * f2.x, d * f2.y);
    __half2 p3 = __floats2half2_rn(d * f3.x, d * f3.y);
    uint4 w;
    w.x = *(unsigned*)&p0; w.y = *(unsigned*)&p1;
    w.z = *(unsigned*)&p2; w.w = *(unsigned*)&p3;
    ((uint4*)g_hsA)[idx] = w;
}

// ---------------- Propagation hop: pair-split half-warp gathers (known-good) ----
__device__ __forceinline__ void acc4(float& a0, float& a1, float& a2, float& a3, uint2 v) {
    float2 fl = __half22float2(*(__half2*)&v.x);
    float2 fh = __half22float2(*(__half2*)&v.y);
    a0 += fl.x; a1 += fl.y; a2 += fh.x; a3 += fh.y;
}

__global__ __launch_bounds__(256) void k_hop(const uint2* __restrict__ hs,
                                             uint2* __restrict__ hn,
                                             int n, int final_hop) {
    int warp = (blockIdx.x * blockDim.x + threadIdx.x) >> 5;
    int lane = threadIdx.x & 31;
    if (warp >= n) return;
    int half = lane >> 4;      // 0 or 1
    int sub  = lane & 15;      // feature group: 4 features each
    int beg = g_colptr[warp], end = g_colptr[warp + 1];

    float a0, a1, a2, a3;
    float b0 = 0.f, b1 = 0.f, b2 = 0.f, b3 = 0.f;
    if (half == 0) {           // self loop counted once
        uint2 s = hs[(size_t)warp * 16 + sub];
        float2 fl = __half22float2(*(__half2*)&s.x);
        float2 fh = __half22float2(*(__half2*)&s.y);
        a0 = fl.x; a1 = fl.y; a2 = fh.x; a3 = fh.y;
    } else {
        a0 = a1 = a2 = a3 = 0.f;
    }

    int e = beg;
    for (; e + 8 <= end; e += 8) {
        int i0 = __ldg(&g_edge[e     + half]);
        int i1 = __ldg(&g_edge[e + 2 + half]);
        int i2 = __ldg(&g_edge[e + 4 + half]);
        int i3 = __ldg(&g_edge[e + 6 + half]);
        uint2 v0 = hs[(size_t)i0 * 16 + sub];
        uint2 v1 = hs[(size_t)i1 * 16 + sub];
        uint2 v2 = hs[(size_t)i2 * 16 + sub];
        uint2 v3 = hs[(size_t)i3 * 16 + sub];
        acc4(a0, a1, a2, a3, v0);
        acc4(b0, b1, b2, b3, v1);
        acc4(a0, a1, a2, a3, v2);
        acc4(b0, b1, b2, b3, v3);
    }
    for (; e + 2 <= end; e += 2) {
        int i0 = __ldg(&g_edge[e + half]);
        uint2 v0 = hs[(size_t)i0 * 16 + sub];
        acc4(a0, a1, a2, a3, v0);
    }
    if (e < end && half == 0) {
        int i0 = __ldg(&g_edge[e]);
        uint2 v0 = hs[(size_t)i0 * 16 + sub];
        acc4(a0, a1, a2, a3, v0);
    }
    a0 += b0; a1 += b1; a2 += b2; a3 += b3;
    a0 += __shfl_xor_sync(0xffffffffu, a0, 16);
    a1 += __shfl_xor_sync(0xffffffffu, a1, 16);
    a2 += __shfl_xor_sync(0xffffffffu, a2, 16);
    a3 += __shfl_xor_sync(0xffffffffu, a3, 16);

    float d = g_dis[warp];
    uint2 hz = *(const uint2*)(g_h0h + (size_t)warp * 32 + sub * 2);
    float2 zl = __half22float2(*(__half2*)&hz.x);
    float2 zh = __half22float2(*(__half2*)&hz.y);
    float o0 = 0.9f * d * a0 + 0.1f * zl.x;
    float o1 = 0.9f * d * a1 + 0.1f * zl.y;
    float o2 = 0.9f * d * a2 + 0.1f * zh.x;
    float o3 = 0.9f * d * a3 + 0.1f * zh.y;

    if (half == 0) {
        if (final_hop) {
            *(float4*)(g_hF + (size_t)warp * HID + sub * 4) = make_float4(o0, o1, o2, o3);
        } else {
            __half2 p0 = __floats2half2_rn(d * o0, d * o1);
            __half2 p1 = __floats2half2_rn(d * o2, d * o3);
            uint2 w;
            w.x = *(unsigned*)&p0;
            w.y = *(unsigned*)&p1;
            hn[(size_t)warp * 16 + sub] = w;
        }
    }
}

// ---------------- Predict + softmax family: 4 nodes/warp, k-outer ----------------
__global__ __launch_bounds__(256) void k_pred(const float* __restrict__ h,
                                              const float* __restrict__ Wp,
                                              const float* __restrict__ bp,
                                              float* __restrict__ out,
                                              int n, int out_size) {
    __shared__ __align__(16) float Ws[HID * NCLS];     // 12 KB
    __shared__ __align__(16) float bs[48];             // padded
    __shared__ __align__(16) float hsm[8][4][HID];     // 8 KB, 16B aligned
    for (int i = threadIdx.x; i < HID * NCLS; i += blockDim.x) Ws[i] = Wp[i];
    if (threadIdx.x < NCLS) bs[threadIdx.x] = bp[threadIdx.x];
    __syncthreads();

    int warp = threadIdx.x >> 5;
    int lane = threadIdx.x & 31;
    int vBase = blockIdx.x * 32 + warp * 4;
    if (vBase >= n) return;

    #pragma unroll
    for (int t = 0; t < 2; t++) {
        int f = lane * 8 + t * 4;       // 0..255, 16B aligned
        int j = f >> 6;
        int k = f & 63;
        int v = vBase + j;
        if (v >= n) v = n - 1;
        float4 val = *(const float4*)(h + (size_t)v * HID + k);
        *(float4*)&hsm[warp][j][k] = val;
    }
    __syncwarp();

    bool l1 = (lane + 32 < NCLS);
    int c1 = l1 ? (lane + 32) : (NCLS - 1);
    float acc0[4], acc1[4];
    #pragma unroll
    for (int j = 0; j < 4; j++) { acc0[j] = bs[lane]; acc1[j] = bs[c1]; }

    #pragma unroll 8
    for (int k = 0; k < HID; k++) {
        float w0 = Ws[k * NCLS + lane];
        float w1 = Ws[k * NCLS + c1];
        #pragma unroll
        for (int j = 0; j < 4; j++) {
            float hk = hsm[warp][j][k];
            acc0[j] += hk * w0;
            acc1[j] += hk * w1;
        }
    }

    size_t sec = (size_t)n * NCLS;
    #pragma unroll
    for (int j = 0; j < 4; j++) {
        int v = vBase + j;
        if (v >= n) break;
        float a0 = acc0[j], a1 = acc1[j];

        float m = fmaxf(a0, l1 ? a1 : -INFINITY);
        #pragma unroll
        for (int o = 16; o > 0; o >>= 1) m = fmaxf(m, __shfl_xor_sync(0xffffffff, m, o));
        float e0 = __expf(a0 - m);
        float e1 = l1 ? __expf(a1 - m) : 0.f;
        float s = e0 + e1;
        #pragma unroll
        for (int o = 16; o > 0; o >>= 1) s += __shfl_xor_sync(0xffffffff, s, o);
        float lse = m + logf(s);
        float inv = 1.f / s;

        size_t base = (size_t)v * NCLS;
        out[base + lane] = a0 - lse;
        if (l1) out[base + lane + 32] = a1 - lse;
        if (out_size >= 2 * (int)sec) {
            out[sec + base + lane] = a0;
            if (l1) out[sec + base + lane + 32] = a1;
        }
        if (out_size >= 3 * (int)sec) {
            out[2 * sec + base + lane] = e0 * inv;
            if (l1) out[2 * sec + base + lane + 32] = e1 * inv;
        }
    }
}

// ---------------- launch ----------------
extern "C" void kernel_launch(void* const* d_in, const int* in_sizes, int n_in,
                              void* d_out, int out_size) {
    const float* x     = (const float*)d_in[0];   // [N,512]
    const int*   eidx  = (const int*)d_in[1];     // [2,E]
    const float* Wemb  = (const float*)d_in[2];   // [512,64]
    const float* bemb  = (const float*)d_in[3];   // [64]
    const float* Wpred = (const float*)d_in[4];   // [64,47]
    const float* bpred = (const float*)d_in[5];   // [47]
    float* out = (float*)d_out;

    int n = in_sizes[0] / FIN;
    int e = in_sizes[1] / 2;
    const int* row = eidx;       // source
    const int* col = eidx + e;   // target

    int nbE  = (e + 255) / 256;
    int nbE4 = (e / 4 + 255) / 256 + 1;
    int nbS  = (n + 1023) / 1024;

    cudaStream_t s2;
    cudaStreamCreate(&s2);
    cudaEvent_t evFork, evEmb;
    cudaEventCreateWithFlags(&evFork, cudaEventDisableTiming);
    cudaEventCreateWithFlags(&evEmb,  cudaEventDisableTiming);
    cudaStream_t s0 = (cudaStream_t)0;

    // fork: side stream runs W conversion + embed GEMM (independent of CSR/dis)
    cudaEventRecord(evFork, s0);
    cudaStreamWaitEvent(s2, evFork, 0);
    k_wconv<<<(FIN * HID + 255) / 256, 256, 0, s2>>>(Wemb);
    k_embed_mma<<<(n + 127) / 128, 256, 0, s2>>>(x, bemb, n);
    cudaEventRecord(evEmb, s2);

    // main: full CSR build chain (overlaps with embed)
    {
        void* cntp; cudaGetSymbolAddress(&cntp, g_count);
        cudaMemsetAsync(cntp, 0, (size_t)n * sizeof(int), s0);
    }
    k_hist<<<nbE4, 256>>>(col, e);
    k_scan_block<<<nbS, 1024>>>(n);   // also computes g_dis
    k_scan_sums<<<1, 32>>>(nbS);
    k_finalize<<<nbS, 1024>>>(n);
    k_scatter_edges<<<nbE, 256>>>(row, col, e);

    // join: hsA scaling needs embed output (side) + dis (main)
    cudaStreamWaitEvent(s0, evEmb, 0);
    k_scale<<<(n * 8 + 255) / 256, 256>>>(n);

    // --- 10 propagation hops (ping-pong fp16 scaled state) ---
    int hopBlocks = (n * 32 + 255) / 256;
    {
        uint2* hAp; cudaGetSymbolAddress((void**)&hAp, g_hsA);
        uint2* hBp; cudaGetSymbolAddress((void**)&hBp, g_hsB);
        uint2* cur = hAp;
        for (int i = 0; i < KHOPS; i++) {
            int fin = (i == KHOPS - 1);
            uint2* dst = (cur == hAp) ? hBp : hAp;
            k_hop<<<hopBlocks, 256>>>(cur, dst, n, fin);
            cur = dst;
        }
    }

    // --- predict + softmax family (reads fp32 g_hF) ---
    float* hFp; cudaGetSymbolAddress((void**)&hFp, g_hF);
    k_pred<<<(n + 31) / 32, 256>>>(hFp, Wpred, bpred, out, n, out_size);
}

// round 15
// speedup vs baseline: 1.0216x; 1.0216x over previous
#include <cuda_runtime.h>
#include <cuda_bf16.h>
#include <cuda_fp16.h>
#include <math.h>

// Problem constants (shapes are fixed for this problem instance)
#define NN      100000
#define NE      3200000
#define FIN     512
#define HID     64
#define NCLS    47
#define KHOPS   10
#define ALPHA   0.1f

// -------- device scratch (no allocations allowed) --------
__device__ int   g_count[NN];        // in-degree counts (real edges only)
__device__ int   g_colptr[NN + 1];   // CSR row pointers (by destination)
__device__ int   g_cursor[NN];       // scatter cursors
__device__ float g_dis[NN];          // D^-1/2 (deg incl. self loop)
__device__ int   g_incl[NN];         // inclusive per-block scan temp
__device__ int   g_blksum[256];      // block sums for scan
__device__ __align__(16) int g_edge[NE + 8];  // src index, sorted by dst (+pad)
__device__ __align__(16) __half g_Wt[(size_t)HID * FIN];  // W^T fp16 [64][512]
__device__ __align__(256) __half2 g_h0h[(size_t)NN * 32]; // fp16 anchor (unscaled h0)
__device__ __align__(256) __half2 g_hsA[(size_t)NN * 32]; // scaled fp16 state
__device__ __align__(256) __half2 g_hsB[(size_t)NN * 32];

// ---------------- CSR build ----------------
__global__ void k_hist(const int* __restrict__ col, int e) {
    int i4 = (blockIdx.x * blockDim.x + threadIdx.x) * 4;
    if (i4 + 4 <= e) {
        int4 c = *(const int4*)(col + i4);
        atomicAdd(&g_count[c.x], 1);
        atomicAdd(&g_count[c.y], 1);
        atomicAdd(&g_count[c.z], 1);
        atomicAdd(&g_count[c.w], 1);
    } else {
        for (int i = i4; i < e; i++) atomicAdd(&g_count[col[i]], 1);
    }
}

// Hillis-Steele block scan (1024/block); also computes g_dis
__global__ void k_scan_block(int n) {
    __shared__ int s[1024];
    int i = blockIdx.x * 1024 + threadIdx.x;
    int v = (i < n) ? g_count[i] : 0;
    if (i < n) g_dis[i] = rsqrtf((float)(v + 1));  // +1 self loop
    s[threadIdx.x] = v;
    __syncthreads();
    #pragma unroll
    for (int off = 1; off < 1024; off <<= 1) {
        int t = (threadIdx.x >= off) ? s[threadIdx.x - off] : 0;
        __syncthreads();
        s[threadIdx.x] += t;
        __syncthreads();
    }
    if (i < n) g_incl[i] = s[threadIdx.x];
    if (threadIdx.x == 1023) g_blksum[blockIdx.x] = s[1023];
}

// warp-parallel exclusive scan of block sums (shfl scan, chunks of 32)
__global__ void k_scan_sums(int nb) {
    int lane = threadIdx.x & 31;
    int carry = 0;
    for (int base = 0; base < nb; base += 32) {
        int i = base + lane;
        int orig = (i < nb) ? g_blksum[i] : 0;
        int v = orig;
        #pragma unroll
        for (int off = 1; off < 32; off <<= 1) {
            int t = __shfl_up_sync(0xffffffffu, v, off);
            if (lane >= off) v += t;
        }
        if (i < nb) g_blksum[i] = (v - orig) + carry;   // exclusive + carry
        carry += __shfl_sync(0xffffffffu, v, 31);       // chunk total
    }
}

__global__ void k_finalize(int n) {
    int i = blockIdx.x * blockDim.x + threadIdx.x;
    if (i == 0) g_colptr[0] = 0;
    if (i < n) {
        int e = g_incl[i] + g_blksum[i >> 10];
        g_colptr[i + 1] = e;
        g_cursor[i] = e - g_count[i];
    }
}

__global__ void k_scatter_edges(const int* __restrict__ row, const int* __restrict__ col, int e) {
    int i = blockIdx.x * blockDim.x + threadIdx.x;
    if (i >= e) return;
    int c = col[i];
    int pos = atomicAdd(&g_cursor[c], 1);
    g_edge[pos] = row[i];
}

// ---------------- W preconvert: g_Wt[n][k] = (half)W[k][n] ----------------
__global__ void k_wconv(const float* __restrict__ W) {
    int i = blockIdx.x * blockDim.x + threadIdx.x;
    if (i < FIN * HID) {
        int k = i >> 6, nn = i & 63;
        g_Wt[(size_t)nn * FIN + k] = __float2half(W[(size_t)k * HID + nn]);
    }
}

// ---------------- Embed GEMM: fused fp32->fp16 reg-staged, double-buffered ------
// (R12-exact form: best measured variant.)
#define KC 32
#define XSTR 40            // smem row stride in halves (80 B, 16B-aligned rows)
#define NCHUNK (FIN / KC)  // 16
__global__ __launch_bounds__(256, 3) void k_embed_mma(const float* __restrict__ X,
                                                      const float* __restrict__ b, int n) {
    __shared__ __align__(16) __half Xs[2][128][XSTR];   // 20.5 KB
    __shared__ __align__(16) __half Ws[2][64][XSTR];    // 10.2 KB
    __shared__ float bs[HID];
    int tid = threadIdx.x;
    int wid = tid >> 5, lane = tid & 31;
    int g  = lane >> 2;          // 0..7
    int cq = (lane & 3) * 2;     // 0,2,4,6
    int rowBase = blockIdx.x * 128;
    if (tid < HID) bs[tid] = b[tid];

    // X: 2 threads/row, 16 consecutive floats each (4x LDG.128)
    int xr = tid >> 1;
    int xp = (tid & 1) * 16;
    int gxr = rowBase + xr;
    if (gxr >= n) gxr = n - 1;   // clamp; epilogue guards writes
    const float4* xsrc = (const float4*)(X + (size_t)gxr * FIN + xp);
    // W: 4 threads/row, 8 halves each (1x LDG.128)
    int wr = tid >> 2;
    int wq = (tid & 3) * 8;
    const uint4* wsrc = (const uint4*)(g_Wt + (size_t)wr * FIN + wq);

    float acc[8][4];
    #pragma unroll
    for (int i = 0; i < 8; i++)
        #pragma unroll
        for (int j = 0; j < 4; j++) acc[i][j] = 0.f;

    float4 xv[4];
    uint4  wv;
    #pragma unroll
    for (int t = 0; t < 4; t++) xv[t] = xsrc[t];
    wv = wsrc[0];

    for (int c = 0; c < NCHUNK; c++) {
        int st = c & 1;
        {
            __half2 h0 = __floats2half2_rn(xv[0].x, xv[0].y);
            __half2 h1 = __floats2half2_rn(xv[0].z, xv[0].w);
            __half2 h2 = __floats2half2_rn(xv[1].x, xv[1].y);
            __half2 h3 = __floats2half2_rn(xv[1].z, xv[1].w);
            __half2 h4 = __floats2half2_rn(xv[2].x, xv[2].y);
            __half2 h5 = __floats2half2_rn(xv[2].z, xv[2].w);
            __half2 h6 = __floats2half2_rn(xv[3].x, xv[3].y);
            __half2 h7 = __floats2half2_rn(xv[3].z, xv[3].w);
            uint4 p0, p1;
            p0.x = *(unsigned*)&h0; p0.y = *(unsigned*)&h1;
            p0.z = *(unsigned*)&h2; p0.w = *(unsigned*)&h3;
            p1.x = *(unsigned*)&h4; p1.y = *(unsigned*)&h5;
            p1.z = *(unsigned*)&h6; p1.w = *(unsigned*)&h7;
            *(uint4*)&Xs[st][xr][xp]     = p0;
            *(uint4*)&Xs[st][xr][xp + 8] = p1;
            *(uint4*)&Ws[st][wr][wq]     = wv;
        }
        __syncthreads();
        if (c + 1 < NCHUNK) {
            const float4* xn = xsrc + (c + 1) * (KC / 4);
            #pragma unroll
            for (int t = 0; t < 4; t++) xv[t] = xn[t];
            wv = wsrc[(c + 1) * (KC / 8)];
        }
        #pragma unroll
        for (int kk = 0; kk < KC; kk += 16) {
            unsigned a0 = *(const unsigned*)&Xs[st][wid * 16 + g][kk + cq];
            unsigned a1 = *(const unsigned*)&Xs[st][wid * 16 + g + 8][kk + cq];
            unsigned a2 = *(const unsigned*)&Xs[st][wid * 16 + g][kk + cq + 8];
            unsigned a3 = *(const unsigned*)&Xs[st][wid * 16 + g + 8][kk + cq + 8];
            #pragma unroll
            for (int cb = 0; cb < 8; cb++) {
                unsigned b0 = *(const unsigned*)&Ws[st][cb * 8 + g][kk + cq];
                unsigned b1 = *(const unsigned*)&Ws[st][cb * 8 + g][kk + cq + 8];
                asm volatile(
                    "mma.sync.aligned.m16n8k16.row.col.f32.f16.f16.f32 "
                    "{%0,%1,%2,%3}, {%4,%5,%6,%7}, {%8,%9}, {%0,%1,%2,%3};"
                    : "+f"(acc[cb][0]), "+f"(acc[cb][1]),
                      "+f"(acc[cb][2]), "+f"(acc[cb][3])
                    : "r"(a0), "r"(a1), "r"(a2), "r"(a3), "r"(b0), "r"(b1));
            }
        }
        __syncthreads();
    }

    // epilogue: bias + relu -> fp16 anchor g_h0h and dis-scaled fp16 state g_hsA
    int r0 = rowBase + wid * 16 + g;
    int r1 = r0 + 8;
    float d0 = (r0 < n) ? g_dis[r0] : 0.f;
    float d1 = (r1 < n) ? g_dis[r1] : 0.f;
    #pragma unroll
    for (int cb = 0; cb < 8; cb++) {
        int c = cb * 8 + cq;
        float bx = bs[c], by = bs[c + 1];
        if (r0 < n) {
            float v0 = fmaxf(acc[cb][0] + bx, 0.f);
            float v1 = fmaxf(acc[cb][1] + by, 0.f);
            g_h0h[(size_t)r0 * 32 + (c >> 1)] = __floats2half2_rn(v0, v1);
            g_hsA[(size_t)r0 * 32 + (c >> 1)] = __floats2half2_rn(d0 * v0, d0 * v1);
        }
        if (r1 < n) {
            float v0 = fmaxf(acc[cb][2] + bx, 0.f);
            float v1 = fmaxf(acc[cb][3] + by, 0.f);
            g_h0h[(size_t)r1 * 32 + (c >> 1)] = __floats2half2_rn(v0, v1);
            g_hsA[(size_t)r1 * 32 + (c >> 1)] = __floats2half2_rn(d1 * v0, d1 * v1);
        }
    }
}

// ---------------- Propagation hop: pair-split half-warp gathers (known-good) ----
// Final hop writes UNSCALED fp16 h into hn (same store path, no d factor);
// pred reads fp16 directly. Saves the fp32 g_hF round trip.
__device__ __forceinline__ void acc4(float& a0, float& a1, float& a2, float& a3, uint2 v) {
    float2 fl = __half22float2(*(__half2*)&v.x);
    float2 fh = __half22float2(*(__half2*)&v.y);
    a0 += fl.x; a1 += fl.y; a2 += fh.x; a3 += fh.y;
}

__global__ __launch_bounds__(256) void k_hop(const uint2* __restrict__ hs,
                                             uint2* __restrict__ hn,
                                             int n, int final_hop) {
    int warp = (blockIdx.x * blockDim.x + threadIdx.x) >> 5;
    int lane = threadIdx.x & 31;
    if (warp >= n) return;
    int half = lane >> 4;      // 0 or 1
    int sub  = lane & 15;      // feature group: 4 features each
    int beg = g_colptr[warp], end = g_colptr[warp + 1];

    float a0, a1, a2, a3;
    float b0 = 0.f, b1 = 0.f, b2 = 0.f, b3 = 0.f;
    if (half == 0) {           // self loop counted once
        uint2 s = hs[(size_t)warp * 16 + sub];
        float2 fl = __half22float2(*(__half2*)&s.x);
        float2 fh = __half22float2(*(__half2*)&s.y);
        a0 = fl.x; a1 = fl.y; a2 = fh.x; a3 = fh.y;
    } else {
        a0 = a1 = a2 = a3 = 0.f;
    }

    int e = beg;
    for (; e + 8 <= end; e += 8) {
        int i0 = __ldg(&g_edge[e     + half]);
        int i1 = __ldg(&g_edge[e + 2 + half]);
        int i2 = __ldg(&g_edge[e + 4 + half]);
        int i3 = __ldg(&g_edge[e + 6 + half]);
        uint2 v0 = hs[(size_t)i0 * 16 + sub];
        uint2 v1 = hs[(size_t)i1 * 16 + sub];
        uint2 v2 = hs[(size_t)i2 * 16 + sub];
        uint2 v3 = hs[(size_t)i3 * 16 + sub];
        acc4(a0, a1, a2, a3, v0);
        acc4(b0, b1, b2, b3, v1);
        acc4(a0, a1, a2, a3, v2);
        acc4(b0, b1, b2, b3, v3);
    }
    for (; e + 2 <= end; e += 2) {
        int i0 = __ldg(&g_edge[e + half]);
        uint2 v0 = hs[(size_t)i0 * 16 + sub];
        acc4(a0, a1, a2, a3, v0);
    }
    if (e < end && half == 0) {
        int i0 = __ldg(&g_edge[e]);
        uint2 v0 = hs[(size_t)i0 * 16 + sub];
        acc4(a0, a1, a2, a3, v0);
    }
    a0 += b0; a1 += b1; a2 += b2; a3 += b3;
    a0 += __shfl_xor_sync(0xffffffffu, a0, 16);
    a1 += __shfl_xor_sync(0xffffffffu, a1, 16);
    a2 += __shfl_xor_sync(0xffffffffu, a2, 16);
    a3 += __shfl_xor_sync(0xffffffffu, a3, 16);

    float d = g_dis[warp];
    uint2 hz = *(const uint2*)(g_h0h + (size_t)warp * 32 + sub * 2);
    float2 zl = __half22float2(*(__half2*)&hz.x);
    float2 zh = __half22float2(*(__half2*)&hz.y);
    float o0 = 0.9f * d * a0 + 0.1f * zl.x;
    float o1 = 0.9f * d * a1 + 0.1f * zl.y;
    float o2 = 0.9f * d * a2 + 0.1f * zh.x;
    float o3 = 0.9f * d * a3 + 0.1f * zh.y;

    if (half == 0) {
        float sc = final_hop ? 1.0f : d;     // final: store unscaled h
        __half2 p0 = __floats2half2_rn(sc * o0, sc * o1);
        __half2 p1 = __floats2half2_rn(sc * o2, sc * o3);
        uint2 w;
        w.x = *(unsigned*)&p0;
        w.y = *(unsigned*)&p1;
        hn[(size_t)warp * 16 + sub] = w;
    }
}

// ---------------- Predict + softmax family: 4 nodes/warp, k-outer, fp16 h -------
__global__ __launch_bounds__(256) void k_pred(const __half* __restrict__ h,
                                              const float* __restrict__ Wp,
                                              const float* __restrict__ bp,
                                              float* __restrict__ out,
                                              int n, int out_size) {
    __shared__ __align__(16) float Ws[HID * NCLS];     // 12 KB
    __shared__ __align__(16) float bs[48];             // padded
    __shared__ __align__(16) float hsm[8][4][HID];     // 8 KB, 16B aligned
    for (int i = threadIdx.x; i < HID * NCLS; i += blockDim.x) Ws[i] = Wp[i];
    if (threadIdx.x < NCLS) bs[threadIdx.x] = bp[threadIdx.x];
    __syncthreads();

    int warp = threadIdx.x >> 5;
    int lane = threadIdx.x & 31;
    int vBase = blockIdx.x * 32 + warp * 4;
    if (vBase >= n) return;

    // load 4 fp16 node rows (256 halves = 512 B): 1 uint4 (8 halves) per lane
    {
        int f = lane * 8;               // half index within 4-row block
        int j = f >> 6;                 // node 0..3
        int k = f & 63;                 // feature 0..56 step 8
        int v = vBase + j;
        if (v >= n) v = n - 1;
        uint4 hv = *(const uint4*)(h + (size_t)v * HID + k);
        float2 f0 = __half22float2(*(__half2*)&hv.x);
        float2 f1 = __half22float2(*(__half2*)&hv.y);
        float2 f2 = __half22float2(*(__half2*)&hv.z);
        float2 f3 = __half22float2(*(__half2*)&hv.w);
        *(float4*)&hsm[warp][j][k]     = make_float4(f0.x, f0.y, f1.x, f1.y);
        *(float4*)&hsm[warp][j][k + 4] = make_float4(f2.x, f2.y, f3.x, f3.y);
    }
    __syncwarp();

    bool l1 = (lane + 32 < NCLS);
    int c1 = l1 ? (lane + 32) : (NCLS - 1);
    float acc0[4], acc1[4];
    #pragma unroll
    for (int j = 0; j < 4; j++) { acc0[j] = bs[lane]; acc1[j] = bs[c1]; }

    #pragma unroll 8
    for (int k = 0; k < HID; k++) {
        float w0 = Ws[k * NCLS + lane];
        float w1 = Ws[k * NCLS + c1];
        #pragma unroll
        for (int j = 0; j < 4; j++) {
            float hk = hsm[warp][j][k];
            acc0[j] += hk * w0;
            acc1[j] += hk * w1;
        }
    }

    size_t sec = (size_t)n * NCLS;
    #pragma unroll
    for (int j = 0; j < 4; j++) {
        int v = vBase + j;
        if (v >= n) break;
        float a0 = acc0[j], a1 = acc1[j];

        float m = fmaxf(a0, l1 ? a1 : -INFINITY);
        #pragma unroll
        for (int o = 16; o > 0; o >>= 1) m = fmaxf(m, __shfl_xor_sync(0xffffffff, m, o));
        float e0 = __expf(a0 - m);
        float e1 = l1 ? __expf(a1 - m) : 0.f;
        float s = e0 + e1;
        #pragma unroll
        for (int o = 16; o > 0; o >>= 1) s += __shfl_xor_sync(0xffffffff, s, o);
        float lse = m + logf(s);
        float inv = 1.f / s;

        size_t base = (size_t)v * NCLS;
        out[base + lane] = a0 - lse;
        if (l1) out[base + lane + 32] = a1 - lse;
        if (out_size >= 2 * (int)sec) {
            out[sec + base + lane] = a0;
            if (l1) out[sec + base + lane + 32] = a1;
        }
        if (out_size >= 3 * (int)sec) {
            out[2 * sec + base + lane] = e0 * inv;
            if (l1) out[2 * sec + base + lane + 32] = e1 * inv;
        }
    }
}

// ---------------- launch ----------------
extern "C" void kernel_launch(void* const* d_in, const int* in_sizes, int n_in,
                              void* d_out, int out_size) {
    const float* x     = (const float*)d_in[0];   // [N,512]
    const int*   eidx  = (const int*)d_in[1];     // [2,E]
    const float* Wemb  = (const float*)d_in[2];   // [512,64]
    const float* bemb  = (const float*)d_in[3];   // [64]
    const float* Wpred = (const float*)d_in[4];   // [64,47]
    const float* bpred = (const float*)d_in[5];   // [47]
    float* out = (float*)d_out;

    int n = in_sizes[0] / FIN;
    int e = in_sizes[1] / 2;
    const int* row = eidx;       // source
    const int* col = eidx + e;   // target

    int nbE  = (e + 255) / 256;
    int nbE4 = (e / 4 + 255) / 256 + 1;
    int nbS  = (n + 1023) / 1024;

    cudaStream_t s2;
    cudaStreamCreate(&s2);
    cudaEvent_t evFork, evDis, evEmb;
    cudaEventCreateWithFlags(&evFork, cudaEventDisableTiming);
    cudaEventCreateWithFlags(&evDis,  cudaEventDisableTiming);
    cudaEventCreateWithFlags(&evEmb,  cudaEventDisableTiming);
    cudaStream_t s0 = (cudaStream_t)0;

    // fork: side stream converts W (depends only on inputs)
    cudaEventRecord(evFork, s0);
    cudaStreamWaitEvent(s2, evFork, 0);
    k_wconv<<<(FIN * HID + 255) / 256, 256, 0, s2>>>(Wemb);

    // main: degree histogram + scan (produces g_dis)
    {
        void* cntp; cudaGetSymbolAddress(&cntp, g_count);
        cudaMemsetAsync(cntp, 0, (size_t)n * sizeof(int), s0);
    }
    k_hist<<<nbE4, 256>>>(col, e);
    k_scan_block<<<nbS, 1024>>>(n);   // also computes g_dis
    cudaEventRecord(evDis, s0);

    // side: embed GEMM (needs g_dis + converted W; reads fp32 X, converts in-kernel)
    cudaStreamWaitEvent(s2, evDis, 0);
    k_embed_mma<<<(n + 127) / 128, 256, 0, s2>>>(x, bemb, n);
    cudaEventRecord(evEmb, s2);

    // main (overlapping with embed): finish CSR build
    k_scan_sums<<<1, 32>>>(nbS);
    k_finalize<<<nbS, 1024>>>(n);
    k_scatter_edges<<<nbE, 256>>>(row, col, e);

    // join
    cudaStreamWaitEvent(s0, evEmb, 0);

    // --- 10 propagation hops (ping-pong fp16 scaled state) ---
    int hopBlocks = (n * 32 + 255) / 256;
    uint2* cur;
    {
        uint2* hAp; cudaGetSymbolAddress((void**)&hAp, g_hsA);
        uint2* hBp; cudaGetSymbolAddress((void**)&hBp, g_hsB);
        cur = hAp;
        for (int i = 0; i < KHOPS; i++) {
            int fin = (i == KHOPS - 1);
            uint2* dst = (cur == hAp) ? hBp : hAp;
            k_hop<<<hopBlocks, 256>>>(cur, dst, n, fin);
            cur = dst;
        }
    }

    // --- predict + softmax family (reads fp16 final h from ping-pong buffer) ---
    k_pred<<<(n + 31) / 32, 256>>>((const __half*)cur, Wpred, bpred, out, n, out_size);
}